// round 3
// baseline (speedup 1.0000x reference)
#include <cuda_runtime.h>

// Problem constants
#define BB  16
#define CC  256
#define HH  64
#define WWW 64
#define HW  4096
#define EE  4
#define HID 128
#define RHD 128

// ---------------- device-global scratch (allowed; no dynamic alloc) ----------
__device__ __align__(16) float g_pooled[BB * CC];
__device__ int   g_expert[BB];
__device__ float g_weight[BB];
__device__ __align__(16) float g_y1[(size_t)BB * HID * HW];   // 32 MB
__device__ __align__(16) float g_y2[(size_t)BB * HID * HW];   // 32 MB

typedef unsigned long long u64;

// ---------------- packed f32x2 helpers (sm_100+ FFMA2) -----------------------
__device__ __forceinline__ u64 pack2(float lo, float hi) {
    u64 r; asm("mov.b64 %0, {%1, %2};" : "=l"(r) : "f"(lo), "f"(hi)); return r;
}
__device__ __forceinline__ void unpack2(u64 v, float& lo, float& hi) {
    asm("mov.b64 {%0, %1}, %2;" : "=f"(lo), "=f"(hi) : "l"(v));
}
__device__ __forceinline__ void fma2(u64& acc, u64 a, u64 b) {
    asm("fma.rn.f32x2 %0, %1, %2, %0;" : "+l"(acc) : "l"(a), "l"(b));
}

// ============================================================================
// Kernel 1: global average pool.  grid = B*C blocks, 256 threads.
// ============================================================================
__global__ void pool_kernel(const float* __restrict__ x) {
    int bc = blockIdx.x;
    const float4* p = (const float4*)(x + (size_t)bc * HW);
    float s = 0.f;
    #pragma unroll
    for (int i = threadIdx.x; i < HW / 4; i += 256) {
        float4 v = p[i];
        s += (v.x + v.y) + (v.z + v.w);
    }
    // block reduce
    __shared__ float red[8];
    #pragma unroll
    for (int o = 16; o > 0; o >>= 1) s += __shfl_down_sync(0xffffffffu, s, o);
    if ((threadIdx.x & 31) == 0) red[threadIdx.x >> 5] = s;
    __syncthreads();
    if (threadIdx.x < 8) {
        s = red[threadIdx.x];
        #pragma unroll
        for (int o = 4; o > 0; o >>= 1) s += __shfl_down_sync(0xffu, s, o);
        if (threadIdx.x == 0) g_pooled[bc] = s * (1.0f / (float)HW);
    }
}

// ============================================================================
// Kernel 2: router MLP + softmax + top-1.  grid = B, 128 threads.
// ============================================================================
__global__ void router_kernel(const float* __restrict__ Wr1, const float* __restrict__ br1,
                              const float* __restrict__ Wr2, const float* __restrict__ br2) {
    int b = blockIdx.x;
    int t = threadIdx.x;
    __shared__ float sp[CC];
    __shared__ float sh[RHD];
    __shared__ float slog[EE];
    sp[t]       = g_pooled[b * CC + t];
    sp[t + 128] = g_pooled[b * CC + t + 128];
    __syncthreads();
    // h = relu(pooled @ Wr1^T + br1)
    {
        float acc = br1[t];
        const float* w = Wr1 + (size_t)t * CC;
        #pragma unroll 8
        for (int c = 0; c < CC; c++) acc = fmaf(sp[c], w[c], acc);
        sh[t] = fmaxf(acc, 0.f);
    }
    __syncthreads();
    if (t < EE) {
        float l = br2[t];
        const float* w = Wr2 + (size_t)t * RHD;
        #pragma unroll 8
        for (int r = 0; r < RHD; r++) l = fmaf(sh[r], w[r], l);
        slog[t] = l;
    }
    __syncthreads();
    if (t == 0) {
        float l0 = slog[0], l1 = slog[1], l2 = slog[2], l3 = slog[3];
        float m = fmaxf(fmaxf(l0, l1), fmaxf(l2, l3));
        float e0 = __expf(l0 - m), e1 = __expf(l1 - m), e2 = __expf(l2 - m), e3 = __expf(l3 - m);
        float s = e0 + e1 + e2 + e3;
        float p[4] = {e0 / s, e1 / s, e2 / s, e3 / s};
        int idx = 0; float v = p[0];
        #pragma unroll
        for (int i = 1; i < 4; i++) { if (p[i] > v) { v = p[i]; idx = i; } }
        g_expert[b] = idx;
        g_weight[b] = v / (v + 1e-9f);      // exact reference renorm semantics
    }
}

// ============================================================================
// Kernel 3: 1x1 conv C->HID with ReLU (GEMM M=128, N=4096, K=256 per batch).
// 128x128 tile per block, BK=16, each thread 8x8 via f32x2.
// grid = (32 pixel tiles, B), 256 threads.
// ============================================================================
__global__ __launch_bounds__(256, 2) void gemm1_kernel(const float* __restrict__ x,
                                                       const float* __restrict__ W1) {
    __shared__ __align__(16) float As[16][128];   // [k][m]
    __shared__ __align__(16) float Bs[16][128];   // [k][n]
    int b  = blockIdx.y;
    int pt = blockIdx.x * 128;
    int e  = g_expert[b];
    const float* W = W1 + (size_t)e * (HID * CC);       // [128][256]
    const float* X = x  + (size_t)b * CC * HW;          // [256][4096]

    u64 acc[8][4];
    #pragma unroll
    for (int i = 0; i < 8; i++)
        #pragma unroll
        for (int j = 0; j < 4; j++) acc[i][j] = 0ULL;

    int tid = threadIdx.x;
    int ty = tid >> 4, tx = tid & 15;
    int am = tid >> 1, ak = (tid & 1) << 3;
    int bk = tid >> 4, bn = (tid & 15) << 3;

    for (int kb = 0; kb < CC; kb += 16) {
        float4 a0 = *(const float4*)(W + (size_t)am * CC + kb + ak);
        float4 a1 = *(const float4*)(W + (size_t)am * CC + kb + ak + 4);
        float4 b0 = *(const float4*)(X + (size_t)(kb + bk) * HW + pt + bn);
        float4 b1 = *(const float4*)(X + (size_t)(kb + bk) * HW + pt + bn + 4);
        As[ak + 0][am] = a0.x; As[ak + 1][am] = a0.y; As[ak + 2][am] = a0.z; As[ak + 3][am] = a0.w;
        As[ak + 4][am] = a1.x; As[ak + 5][am] = a1.y; As[ak + 6][am] = a1.z; As[ak + 7][am] = a1.w;
        *(float4*)&Bs[bk][bn]     = b0;
        *(float4*)&Bs[bk][bn + 4] = b1;
        __syncthreads();
        #pragma unroll
        for (int k = 0; k < 16; k++) {
            float af[8];
            *(float4*)&af[0] = *(const float4*)&As[k][ty * 8];
            *(float4*)&af[4] = *(const float4*)&As[k][ty * 8 + 4];
            u64 bv[4];
            #pragma unroll
            for (int j = 0; j < 4; j++) bv[j] = *(const u64*)&Bs[k][tx * 8 + 2 * j];
            #pragma unroll
            for (int i = 0; i < 8; i++) {
                u64 av = pack2(af[i], af[i]);
                #pragma unroll
                for (int j = 0; j < 4; j++) fma2(acc[i][j], av, bv[j]);
            }
        }
        __syncthreads();
    }
    float* Y = g_y1 + (size_t)b * HID * HW + pt;
    #pragma unroll
    for (int i = 0; i < 8; i++) {
        float o8[8];
        #pragma unroll
        for (int j = 0; j < 4; j++) {
            float lo, hi; unpack2(acc[i][j], lo, hi);
            o8[2 * j]     = fmaxf(lo, 0.f);
            o8[2 * j + 1] = fmaxf(hi, 0.f);
        }
        float4* dst = (float4*)(Y + (size_t)(ty * 8 + i) * HW + tx * 8);
        dst[0] = *(float4*)&o8[0];
        dst[1] = *(float4*)&o8[4];
    }
}

// ============================================================================
// Kernel 4: 3x3 conv HID->HID with ReLU (per-batch selected expert).
// Block: 32 out-ch x 16x16 spatial tile, loop IC in chunks of 16.
// Thread: 4 oc x 8 px (one half-row). grid = (16 tiles, 4 ocb, B), 256 thr.
// ============================================================================
__global__ __launch_bounds__(256, 2) void conv3_kernel(const float* __restrict__ W2) {
    __shared__ float sin_[16][18][18];   // [ic][y][x] with halo
    __shared__ float sw[32][16][9];      // [oc][ic][tap]
    int b   = blockIdx.z;
    int ocb = blockIdx.y * 32;
    int ty0 = (blockIdx.x >> 2) << 4;
    int tx0 = (blockIdx.x & 3) << 4;
    int e   = g_expert[b];
    const float* W  = W2   + (size_t)e * HID * HID * 9;  // [oc][ic][9]
    const float* Y1 = g_y1 + (size_t)b * HID * HW;

    int tid = threadIdx.x;
    int ocg = tid >> 5;            // 0..7 : warp-uniform oc group
    int pxg = tid & 31;
    int r   = pxg >> 1;            // row in tile 0..15
    int ch  = (pxg & 1) << 3;      // col base 0 or 8

    u64 acc[4][4];
    #pragma unroll
    for (int o = 0; o < 4; o++)
        #pragma unroll
        for (int j = 0; j < 4; j++) acc[o][j] = 0ULL;

    for (int kcb = 0; kcb < HID; kcb += 16) {
        __syncthreads();
        // input tile with halo (zero padding at image borders)
        for (int idx = tid; idx < 16 * 18 * 18; idx += 256) {
            int c  = idx / 324; int rem = idx - c * 324;
            int iy = rem / 18;  int ix  = rem - iy * 18;
            int gy = ty0 + iy - 1, gx = tx0 + ix - 1;
            float v = 0.f;
            if ((unsigned)gy < 64u && (unsigned)gx < 64u)
                v = Y1[(size_t)(kcb + c) * HW + gy * 64 + gx];
            sin_[c][iy][ix] = v;
        }
        // weights
        for (int idx = tid; idx < 32 * 16 * 9; idx += 256) {
            int oc = idx / 144; int rem = idx - oc * 144;
            int ic = rem / 9;   int tap = rem - ic * 9;
            sw[oc][ic][tap] = W[((size_t)(ocb + oc) * HID + (kcb + ic)) * 9 + tap];
        }
        __syncthreads();
        #pragma unroll 2
        for (int kc = 0; kc < 16; kc++) {
            float inv[3][10];
            #pragma unroll
            for (int dy = 0; dy < 3; dy++)
                #pragma unroll
                for (int dx = 0; dx < 10; dx++)
                    inv[dy][dx] = sin_[kc][r + dy][ch + dx];
            #pragma unroll
            for (int ky = 0; ky < 3; ky++) {
                #pragma unroll
                for (int kx = 0; kx < 3; kx++) {
                    u64 ip[4];
                    #pragma unroll
                    for (int j = 0; j < 4; j++)
                        ip[j] = pack2(inv[ky][kx + 2 * j], inv[ky][kx + 2 * j + 1]);
                    #pragma unroll
                    for (int o = 0; o < 4; o++) {
                        float wv = sw[ocg * 4 + o][kc][ky * 3 + kx];  // warp broadcast
                        u64 wp = pack2(wv, wv);
                        #pragma unroll
                        for (int j = 0; j < 4; j++) fma2(acc[o][j], wp, ip[j]);
                    }
                }
            }
        }
    }
    float* Y2 = g_y2 + (size_t)b * HID * HW;
    int pix = (ty0 + r) * 64 + tx0 + ch;
    #pragma unroll
    for (int o = 0; o < 4; o++) {
        float o8[8];
        #pragma unroll
        for (int j = 0; j < 4; j++) {
            float lo, hi; unpack2(acc[o][j], lo, hi);
            o8[2 * j]     = fmaxf(lo, 0.f);
            o8[2 * j + 1] = fmaxf(hi, 0.f);
        }
        float4* d = (float4*)(Y2 + (size_t)(ocb + ocg * 4 + o) * HW + pix);
        d[0] = *(float4*)&o8[0];
        d[1] = *(float4*)&o8[4];
    }
}

// ============================================================================
// Kernel 5: 1x1 conv HID->C, scaled by routing weight, + residual.
// GEMM M=256, N=4096, K=128. grid = (32 pixel tiles, 2 m tiles, B).
// ============================================================================
__global__ __launch_bounds__(256, 2) void gemm3_kernel(const float* __restrict__ x,
                                                       const float* __restrict__ W3,
                                                       float* __restrict__ out) {
    __shared__ __align__(16) float As[16][128];
    __shared__ __align__(16) float Bs[16][128];
    int b  = blockIdx.z;
    int m0 = blockIdx.y * 128;
    int pt = blockIdx.x * 128;
    int e  = g_expert[b];
    float wgt = g_weight[b];
    const float* W  = W3   + (size_t)e * (CC * HID) + (size_t)m0 * HID;   // [128 rows][128]
    const float* Y2 = g_y2 + (size_t)b * HID * HW;

    u64 acc[8][4];
    #pragma unroll
    for (int i = 0; i < 8; i++)
        #pragma unroll
        for (int j = 0; j < 4; j++) acc[i][j] = 0ULL;

    int tid = threadIdx.x;
    int ty = tid >> 4, tx = tid & 15;
    int am = tid >> 1, ak = (tid & 1) << 3;
    int bk = tid >> 4, bn = (tid & 15) << 3;

    for (int kb = 0; kb < HID; kb += 16) {
        float4 a0 = *(const float4*)(W + (size_t)am * HID + kb + ak);
        float4 a1 = *(const float4*)(W + (size_t)am * HID + kb + ak + 4);
        float4 b0 = *(const float4*)(Y2 + (size_t)(kb + bk) * HW + pt + bn);
        float4 b1 = *(const float4*)(Y2 + (size_t)(kb + bk) * HW + pt + bn + 4);
        As[ak + 0][am] = a0.x; As[ak + 1][am] = a0.y; As[ak + 2][am] = a0.z; As[ak + 3][am] = a0.w;
        As[ak + 4][am] = a1.x; As[ak + 5][am] = a1.y; As[ak + 6][am] = a1.z; As[ak + 7][am] = a1.w;
        *(float4*)&Bs[bk][bn]     = b0;
        *(float4*)&Bs[bk][bn + 4] = b1;
        __syncthreads();
        #pragma unroll
        for (int k = 0; k < 16; k++) {
            float af[8];
            *(float4*)&af[0] = *(const float4*)&As[k][ty * 8];
            *(float4*)&af[4] = *(const float4*)&As[k][ty * 8 + 4];
            u64 bv[4];
            #pragma unroll
            for (int j = 0; j < 4; j++) bv[j] = *(const u64*)&Bs[k][tx * 8 + 2 * j];
            #pragma unroll
            for (int i = 0; i < 8; i++) {
                u64 av = pack2(af[i], af[i]);
                #pragma unroll
                for (int j = 0; j < 4; j++) fma2(acc[i][j], av, bv[j]);
            }
        }
        __syncthreads();
    }
    const float* Xr = x   + (size_t)b * CC * HW + pt;
    float*       O  = out + (size_t)b * CC * HW + pt;
    #pragma unroll
    for (int i = 0; i < 8; i++) {
        int m = m0 + ty * 8 + i;
        float o8[8];
        #pragma unroll
        for (int j = 0; j < 4; j++) {
            float lo, hi; unpack2(acc[i][j], lo, hi);
            o8[2 * j]     = wgt * lo;
            o8[2 * j + 1] = wgt * hi;
        }
        float4 x0 = *(const float4*)(Xr + (size_t)m * HW + tx * 8);
        float4 x1 = *(const float4*)(Xr + (size_t)m * HW + tx * 8 + 4);
        float4 r0, r1;
        r0.x = o8[0] + x0.x; r0.y = o8[1] + x0.y; r0.z = o8[2] + x0.z; r0.w = o8[3] + x0.w;
        r1.x = o8[4] + x1.x; r1.y = o8[5] + x1.y; r1.z = o8[6] + x1.z; r1.w = o8[7] + x1.w;
        *(float4*)(O + (size_t)m * HW + tx * 8)     = r0;
        *(float4*)(O + (size_t)m * HW + tx * 8 + 4) = r1;
    }
}

// ============================================================================
extern "C" void kernel_launch(void* const* d_in, const int* in_sizes, int n_in,
                              void* d_out, int out_size) {
    const float* x   = (const float*)d_in[0];
    const float* Wr1 = (const float*)d_in[1];
    const float* br1 = (const float*)d_in[2];
    const float* Wr2 = (const float*)d_in[3];
    const float* br2 = (const float*)d_in[4];
    const float* W1  = (const float*)d_in[5];
    const float* W2  = (const float*)d_in[6];
    const float* W3  = (const float*)d_in[7];
    float* out = (float*)d_out;

    pool_kernel  <<<BB * CC, 256>>>(x);
    router_kernel<<<BB, 128>>>(Wr1, br1, Wr2, br2);
    gemm1_kernel <<<dim3(32, BB), 256>>>(x, W1);
    conv3_kernel <<<dim3(16, 4, BB), 256>>>(W2);
    gemm3_kernel <<<dim3(32, 2, BB), 256>>>(x, W3, out);
}

// round 4
// speedup vs baseline: 1.0500x; 1.0500x over previous
#include <cuda_runtime.h>

// Problem constants
#define BB  16
#define CC  256
#define HH  64
#define WWW 64
#define HW  4096
#define EE  4
#define HID 128
#define RHD 128

// ---------------- device-global scratch (allowed; no dynamic alloc) ----------
__device__ __align__(16) float g_pooled[BB * CC];
__device__ int   g_expert[BB];
__device__ float g_weight[BB];
__device__ __align__(16) float g_y1[(size_t)BB * HID * HW];   // 32 MB
__device__ __align__(16) float g_y2[(size_t)BB * HID * HW];   // 32 MB

typedef unsigned long long u64;

// ---------------- packed f32x2 helpers (sm_100+ FFMA2) -----------------------
__device__ __forceinline__ u64 pack2(float lo, float hi) {
    u64 r; asm("mov.b64 %0, {%1, %2};" : "=l"(r) : "f"(lo), "f"(hi)); return r;
}
__device__ __forceinline__ void unpack2(u64 v, float& lo, float& hi) {
    asm("mov.b64 {%0, %1}, %2;" : "=f"(lo), "=f"(hi) : "l"(v));
}
__device__ __forceinline__ void fma2(u64& acc, u64 a, u64 b) {
    asm("fma.rn.f32x2 %0, %1, %2, %0;" : "+l"(acc) : "l"(a), "l"(b));
}

// ============================================================================
// Kernel 1: global average pool.  grid = B*C blocks, 256 threads.
// ============================================================================
__global__ void pool_kernel(const float* __restrict__ x) {
    int bc = blockIdx.x;
    const float4* p = (const float4*)(x + (size_t)bc * HW);
    float s = 0.f;
    #pragma unroll
    for (int i = threadIdx.x; i < HW / 4; i += 256) {
        float4 v = p[i];
        s += (v.x + v.y) + (v.z + v.w);
    }
    // block reduce
    __shared__ float red[8];
    #pragma unroll
    for (int o = 16; o > 0; o >>= 1) s += __shfl_down_sync(0xffffffffu, s, o);
    if ((threadIdx.x & 31) == 0) red[threadIdx.x >> 5] = s;
    __syncthreads();
    if (threadIdx.x < 8) {
        s = red[threadIdx.x];
        #pragma unroll
        for (int o = 4; o > 0; o >>= 1) s += __shfl_down_sync(0xffu, s, o);
        if (threadIdx.x == 0) g_pooled[bc] = s * (1.0f / (float)HW);
    }
}

// ============================================================================
// Kernel 2: router MLP + softmax + top-1.  grid = B, 128 threads.
// ============================================================================
__global__ void router_kernel(const float* __restrict__ Wr1, const float* __restrict__ br1,
                              const float* __restrict__ Wr2, const float* __restrict__ br2) {
    int b = blockIdx.x;
    int t = threadIdx.x;
    __shared__ float sp[CC];
    __shared__ float sh[RHD];
    __shared__ float slog[EE];
    sp[t]       = g_pooled[b * CC + t];
    sp[t + 128] = g_pooled[b * CC + t + 128];
    __syncthreads();
    // h = relu(pooled @ Wr1^T + br1)
    {
        float acc = br1[t];
        const float* w = Wr1 + (size_t)t * CC;
        #pragma unroll 8
        for (int c = 0; c < CC; c++) acc = fmaf(sp[c], w[c], acc);
        sh[t] = fmaxf(acc, 0.f);
    }
    __syncthreads();
    if (t < EE) {
        float l = br2[t];
        const float* w = Wr2 + (size_t)t * RHD;
        #pragma unroll 8
        for (int r = 0; r < RHD; r++) l = fmaf(sh[r], w[r], l);
        slog[t] = l;
    }
    __syncthreads();
    if (t == 0) {
        float l0 = slog[0], l1 = slog[1], l2 = slog[2], l3 = slog[3];
        float m = fmaxf(fmaxf(l0, l1), fmaxf(l2, l3));
        float e0 = __expf(l0 - m), e1 = __expf(l1 - m), e2 = __expf(l2 - m), e3 = __expf(l3 - m);
        float s = e0 + e1 + e2 + e3;
        float p[4] = {e0 / s, e1 / s, e2 / s, e3 / s};
        int idx = 0; float v = p[0];
        #pragma unroll
        for (int i = 1; i < 4; i++) { if (p[i] > v) { v = p[i]; idx = i; } }
        g_expert[b] = idx;
        g_weight[b] = v / (v + 1e-9f);      // exact reference renorm semantics
    }
}

// ============================================================================
// Kernel 3: 1x1 conv C->HID with ReLU (GEMM M=128, N=4096, K=256 per batch).
// 128x128 tile per block, BK=16, each thread 8x8 via f32x2.
// grid = (32 pixel tiles, B), 256 threads.
// ============================================================================
__global__ __launch_bounds__(256, 2) void gemm1_kernel(const float* __restrict__ x,
                                                       const float* __restrict__ W1) {
    __shared__ __align__(16) float As[16][128];   // [k][m]
    __shared__ __align__(16) float Bs[16][128];   // [k][n]
    int b  = blockIdx.y;
    int pt = blockIdx.x * 128;
    int e  = g_expert[b];
    const float* W = W1 + (size_t)e * (HID * CC);       // [128][256]
    const float* X = x  + (size_t)b * CC * HW;          // [256][4096]

    u64 acc[8][4];
    #pragma unroll
    for (int i = 0; i < 8; i++)
        #pragma unroll
        for (int j = 0; j < 4; j++) acc[i][j] = 0ULL;

    int tid = threadIdx.x;
    int ty = tid >> 4, tx = tid & 15;
    int am = tid >> 1, ak = (tid & 1) << 3;
    int bk = tid >> 4, bn = (tid & 15) << 3;

    for (int kb = 0; kb < CC; kb += 16) {
        float4 a0 = *(const float4*)(W + (size_t)am * CC + kb + ak);
        float4 a1 = *(const float4*)(W + (size_t)am * CC + kb + ak + 4);
        float4 b0 = *(const float4*)(X + (size_t)(kb + bk) * HW + pt + bn);
        float4 b1 = *(const float4*)(X + (size_t)(kb + bk) * HW + pt + bn + 4);
        As[ak + 0][am] = a0.x; As[ak + 1][am] = a0.y; As[ak + 2][am] = a0.z; As[ak + 3][am] = a0.w;
        As[ak + 4][am] = a1.x; As[ak + 5][am] = a1.y; As[ak + 6][am] = a1.z; As[ak + 7][am] = a1.w;
        *(float4*)&Bs[bk][bn]     = b0;
        *(float4*)&Bs[bk][bn + 4] = b1;
        __syncthreads();
        #pragma unroll
        for (int k = 0; k < 16; k++) {
            float af[8];
            *(float4*)&af[0] = *(const float4*)&As[k][ty * 8];
            *(float4*)&af[4] = *(const float4*)&As[k][ty * 8 + 4];
            u64 bv[4];
            #pragma unroll
            for (int j = 0; j < 4; j++) bv[j] = *(const u64*)&Bs[k][tx * 8 + 2 * j];
            #pragma unroll
            for (int i = 0; i < 8; i++) {
                u64 av = pack2(af[i], af[i]);
                #pragma unroll
                for (int j = 0; j < 4; j++) fma2(acc[i][j], av, bv[j]);
            }
        }
        __syncthreads();
    }
    float* Y = g_y1 + (size_t)b * HID * HW + pt;
    #pragma unroll
    for (int i = 0; i < 8; i++) {
        float o8[8];
        #pragma unroll
        for (int j = 0; j < 4; j++) {
            float lo, hi; unpack2(acc[i][j], lo, hi);
            o8[2 * j]     = fmaxf(lo, 0.f);
            o8[2 * j + 1] = fmaxf(hi, 0.f);
        }
        float4* dst = (float4*)(Y + (size_t)(ty * 8 + i) * HW + tx * 8);
        dst[0] = *(float4*)&o8[0];
        dst[1] = *(float4*)&o8[4];
    }
}

// ============================================================================
// Kernel 4: 3x3 conv HID->HID with ReLU (per-batch selected expert).
// Block: 32 out-ch x 16x16 spatial tile, loop IC in chunks of 16.
// Thread: 4 oc x 8 px (one half-row). grid = (16 tiles, 4 ocb, B), 256 thr.
// ============================================================================
__global__ __launch_bounds__(256, 2) void conv3_kernel(const float* __restrict__ W2) {
    __shared__ float sin_[16][18][18];   // [ic][y][x] with halo
    __shared__ float sw[32][16][9];      // [oc][ic][tap]
    int b   = blockIdx.z;
    int ocb = blockIdx.y * 32;
    int ty0 = (blockIdx.x >> 2) << 4;
    int tx0 = (blockIdx.x & 3) << 4;
    int e   = g_expert[b];
    const float* W  = W2   + (size_t)e * HID * HID * 9;  // [oc][ic][9]
    const float* Y1 = g_y1 + (size_t)b * HID * HW;

    int tid = threadIdx.x;
    int ocg = tid >> 5;            // 0..7 : warp-uniform oc group
    int pxg = tid & 31;
    int r   = pxg >> 1;            // row in tile 0..15
    int ch  = (pxg & 1) << 3;      // col base 0 or 8

    u64 acc[4][4];
    #pragma unroll
    for (int o = 0; o < 4; o++)
        #pragma unroll
        for (int j = 0; j < 4; j++) acc[o][j] = 0ULL;

    for (int kcb = 0; kcb < HID; kcb += 16) {
        __syncthreads();
        // input tile with halo (zero padding at image borders)
        for (int idx = tid; idx < 16 * 18 * 18; idx += 256) {
            int c  = idx / 324; int rem = idx - c * 324;
            int iy = rem / 18;  int ix  = rem - iy * 18;
            int gy = ty0 + iy - 1, gx = tx0 + ix - 1;
            float v = 0.f;
            if ((unsigned)gy < 64u && (unsigned)gx < 64u)
                v = Y1[(size_t)(kcb + c) * HW + gy * 64 + gx];
            sin_[c][iy][ix] = v;
        }
        // weights
        for (int idx = tid; idx < 32 * 16 * 9; idx += 256) {
            int oc = idx / 144; int rem = idx - oc * 144;
            int ic = rem / 9;   int tap = rem - ic * 9;
            sw[oc][ic][tap] = W[((size_t)(ocb + oc) * HID + (kcb + ic)) * 9 + tap];
        }
        __syncthreads();
        #pragma unroll 2
        for (int kc = 0; kc < 16; kc++) {
            float inv[3][10];
            #pragma unroll
            for (int dy = 0; dy < 3; dy++)
                #pragma unroll
                for (int dx = 0; dx < 10; dx++)
                    inv[dy][dx] = sin_[kc][r + dy][ch + dx];
            #pragma unroll
            for (int ky = 0; ky < 3; ky++) {
                #pragma unroll
                for (int kx = 0; kx < 3; kx++) {
                    u64 ip[4];
                    #pragma unroll
                    for (int j = 0; j < 4; j++)
                        ip[j] = pack2(inv[ky][kx + 2 * j], inv[ky][kx + 2 * j + 1]);
                    #pragma unroll
                    for (int o = 0; o < 4; o++) {
                        float wv = sw[ocg * 4 + o][kc][ky * 3 + kx];  // warp broadcast
                        u64 wp = pack2(wv, wv);
                        #pragma unroll
                        for (int j = 0; j < 4; j++) fma2(acc[o][j], wp, ip[j]);
                    }
                }
            }
        }
    }
    float* Y2 = g_y2 + (size_t)b * HID * HW;
    int pix = (ty0 + r) * 64 + tx0 + ch;
    #pragma unroll
    for (int o = 0; o < 4; o++) {
        float o8[8];
        #pragma unroll
        for (int j = 0; j < 4; j++) {
            float lo, hi; unpack2(acc[o][j], lo, hi);
            o8[2 * j]     = fmaxf(lo, 0.f);
            o8[2 * j + 1] = fmaxf(hi, 0.f);
        }
        float4* d = (float4*)(Y2 + (size_t)(ocb + ocg * 4 + o) * HW + pix);
        d[0] = *(float4*)&o8[0];
        d[1] = *(float4*)&o8[4];
    }
}

// ============================================================================
// Kernel 5: 1x1 conv HID->C, scaled by routing weight, + residual.
// GEMM M=256, N=4096, K=128. grid = (32 pixel tiles, 2 m tiles, B).
// ============================================================================
__global__ __launch_bounds__(256, 2) void gemm3_kernel(const float* __restrict__ x,
                                                       const float* __restrict__ W3,
                                                       float* __restrict__ out) {
    __shared__ __align__(16) float As[16][128];
    __shared__ __align__(16) float Bs[16][128];
    int b  = blockIdx.z;
    int m0 = blockIdx.y * 128;
    int pt = blockIdx.x * 128;
    int e  = g_expert[b];
    float wgt = g_weight[b];
    const float* W  = W3   + (size_t)e * (CC * HID) + (size_t)m0 * HID;   // [128 rows][128]
    const float* Y2 = g_y2 + (size_t)b * HID * HW;

    u64 acc[8][4];
    #pragma unroll
    for (int i = 0; i < 8; i++)
        #pragma unroll
        for (int j = 0; j < 4; j++) acc[i][j] = 0ULL;

    int tid = threadIdx.x;
    int ty = tid >> 4, tx = tid & 15;
    int am = tid >> 1, ak = (tid & 1) << 3;
    int bk = tid >> 4, bn = (tid & 15) << 3;

    for (int kb = 0; kb < HID; kb += 16) {
        float4 a0 = *(const float4*)(W + (size_t)am * HID + kb + ak);
        float4 a1 = *(const float4*)(W + (size_t)am * HID + kb + ak + 4);
        float4 b0 = *(const float4*)(Y2 + (size_t)(kb + bk) * HW + pt + bn);
        float4 b1 = *(const float4*)(Y2 + (size_t)(kb + bk) * HW + pt + bn + 4);
        As[ak + 0][am] = a0.x; As[ak + 1][am] = a0.y; As[ak + 2][am] = a0.z; As[ak + 3][am] = a0.w;
        As[ak + 4][am] = a1.x; As[ak + 5][am] = a1.y; As[ak + 6][am] = a1.z; As[ak + 7][am] = a1.w;
        *(float4*)&Bs[bk][bn]     = b0;
        *(float4*)&Bs[bk][bn + 4] = b1;
        __syncthreads();
        #pragma unroll
        for (int k = 0; k < 16; k++) {
            float af[8];
            *(float4*)&af[0] = *(const float4*)&As[k][ty * 8];
            *(float4*)&af[4] = *(const float4*)&As[k][ty * 8 + 4];
            u64 bv[4];
            #pragma unroll
            for (int j = 0; j < 4; j++) bv[j] = *(const u64*)&Bs[k][tx * 8 + 2 * j];
            #pragma unroll
            for (int i = 0; i < 8; i++) {
                u64 av = pack2(af[i], af[i]);
                #pragma unroll
                for (int j = 0; j < 4; j++) fma2(acc[i][j], av, bv[j]);
            }
        }
        __syncthreads();
    }
    const float* Xr = x   + (size_t)b * CC * HW + pt;
    float*       O  = out + (size_t)b * CC * HW + pt;
    #pragma unroll
    for (int i = 0; i < 8; i++) {
        int m = m0 + ty * 8 + i;
        float o8[8];
        #pragma unroll
        for (int j = 0; j < 4; j++) {
            float lo, hi; unpack2(acc[i][j], lo, hi);
            o8[2 * j]     = wgt * lo;
            o8[2 * j + 1] = wgt * hi;
        }
        float4 x0 = *(const float4*)(Xr + (size_t)m * HW + tx * 8);
        float4 x1 = *(const float4*)(Xr + (size_t)m * HW + tx * 8 + 4);
        float4 r0, r1;
        r0.x = o8[0] + x0.x; r0.y = o8[1] + x0.y; r0.z = o8[2] + x0.z; r0.w = o8[3] + x0.w;
        r1.x = o8[4] + x1.x; r1.y = o8[5] + x1.y; r1.z = o8[6] + x1.z; r1.w = o8[7] + x1.w;
        *(float4*)(O + (size_t)m * HW + tx * 8)     = r0;
        *(float4*)(O + (size_t)m * HW + tx * 8 + 4) = r1;
    }
}

// ============================================================================
extern "C" void kernel_launch(void* const* d_in, const int* in_sizes, int n_in,
                              void* d_out, int out_size) {
    const float* x   = (const float*)d_in[0];
    const float* Wr1 = (const float*)d_in[1];
    const float* br1 = (const float*)d_in[2];
    const float* Wr2 = (const float*)d_in[3];
    const float* br2 = (const float*)d_in[4];
    const float* W1  = (const float*)d_in[5];
    const float* W2  = (const float*)d_in[6];
    const float* W3  = (const float*)d_in[7];
    float* out = (float*)d_out;

    pool_kernel  <<<BB * CC, 256>>>(x);
    router_kernel<<<BB, 128>>>(Wr1, br1, Wr2, br2);
    gemm1_kernel <<<dim3(32, BB), 256>>>(x, W1);
    conv3_kernel <<<dim3(16, 4, BB), 256>>>(W2);
    gemm3_kernel <<<dim3(32, 2, BB), 256>>>(x, W3, out);
}